// round 1
// baseline (speedup 1.0000x reference)
#include <cuda_runtime.h>
#include <cuda_bf16.h>

// Problem constants (verified against metadata: u [N,64] f32, w [32,40], h [32,40],
// d [32,39], nodes [32] i32; out = concat(x [N,64], logd [N]) f32).
#define D_    32
#define K_    40
#define DTOT_ 64
#define B_    5.0f

// Precomputed per-dim spline tables (tiny).
__device__ float g_cumw [D_ * (K_ + 1)];
__device__ float g_invbw[D_ * K_];
__device__ float g_ch   [D_ * K_];      // cumh[idx]
__device__ float g_bh   [D_ * K_];      // heights[idx]
__device__ float g_delta[D_ * K_];      // bh / bw
__device__ float g_dv   [D_ * (K_ + 1)];// derivatives (1, softplus(d), 1)
__device__ int   g_colmap[DTOT_];       // column -> spline dim j, or -1

__global__ void precompute_tables(const float* __restrict__ w,
                                  const float* __restrict__ h,
                                  const float* __restrict__ d,
                                  const int*   __restrict__ nodes) {
    int j = threadIdx.x;
    if (j == 0) {
        for (int c = 0; c < DTOT_; c++) g_colmap[c] = -1;
    }
    __syncthreads();
    if (j >= D_) return;
    g_colmap[nodes[j]] = j;

    // ---- widths = softmax(w[j]) * 2B ; cumw = -B + cumsum ----
    float e[K_];
    {
        float m = -1e30f;
        for (int i = 0; i < K_; i++) m = fmaxf(m, w[j * K_ + i]);
        float s = 0.f;
        for (int i = 0; i < K_; i++) { e[i] = expf(w[j * K_ + i] - m); s += e[i]; }
        float scl = (2.0f * B_) / s;
        float c = -B_;
        for (int i = 0; i < K_; i++) {
            g_cumw[j * (K_ + 1) + i] = c;
            float bw = e[i] * scl;
            g_invbw[j * K_ + i] = 1.0f / bw;
            c += bw;
        }
        g_cumw[j * (K_ + 1) + K_] = c;
    }
    // ---- heights = softmax(h[j]) * 2B ; cumh ; bh ; delta ----
    {
        float m = -1e30f;
        for (int i = 0; i < K_; i++) m = fmaxf(m, h[j * K_ + i]);
        float s = 0.f;
        for (int i = 0; i < K_; i++) { e[i] = expf(h[j * K_ + i] - m); s += e[i]; }
        float scl = (2.0f * B_) / s;
        float c = -B_;
        for (int i = 0; i < K_; i++) {
            float bh = e[i] * scl;
            g_ch[j * K_ + i] = c;
            g_bh[j * K_ + i] = bh;
            g_delta[j * K_ + i] = bh * g_invbw[j * K_ + i];
            c += bh;
        }
    }
    // ---- derivatives: [1, softplus(d), 1] ----
    g_dv[j * (K_ + 1) + 0]  = 1.0f;
    g_dv[j * (K_ + 1) + K_] = 1.0f;
    for (int i = 0; i < K_ - 1; i++) {
        float x = d[j * (K_ - 1) + i];
        g_dv[j * (K_ + 1) + 1 + i] = log1pf(expf(x));  // softplus; |x|<=0.5 so no overflow path needed
    }
}

// One warp per row. Lane l handles columns l and l+32 (both coalesced).
__global__ void __launch_bounds__(256)
spline_kernel(const float* __restrict__ u,
              float* __restrict__ xout,
              float* __restrict__ logd,
              int N) {
    __shared__ float s_cumw [D_ * (K_ + 1)];
    __shared__ float s_invbw[D_ * K_];
    __shared__ float s_ch   [D_ * K_];
    __shared__ float s_bh   [D_ * K_];
    __shared__ float s_delta[D_ * K_];
    __shared__ float s_dv   [D_ * (K_ + 1)];
    __shared__ int   s_colmap[DTOT_];

    for (int i = threadIdx.x; i < D_ * (K_ + 1); i += blockDim.x) {
        s_cumw[i] = g_cumw[i];
        s_dv[i]   = g_dv[i];
    }
    for (int i = threadIdx.x; i < D_ * K_; i += blockDim.x) {
        s_invbw[i] = g_invbw[i];
        s_ch[i]    = g_ch[i];
        s_bh[i]    = g_bh[i];
        s_delta[i] = g_delta[i];
    }
    if (threadIdx.x < DTOT_) s_colmap[threadIdx.x] = g_colmap[threadIdx.x];
    __syncthreads();

    const int lane = threadIdx.x & 31;
    const int warp = threadIdx.x >> 5;
    const int row  = blockIdx.x * 8 + warp;
    if (row >= N) return;

    const size_t base = (size_t)row * DTOT_;
    float acc = 0.0f;
    float res[2];

#pragma unroll
    for (int half = 0; half < 2; half++) {
        const int col = lane + half * 32;
        const float x = u[base + col];
        float y = x;
        const int j = s_colmap[col];
        if (j >= 0 && fabsf(x) <= B_) {
            const float xc = fminf(fmaxf(x, -B_), B_);
            // searchsorted(cumw, xc, 'right') - 1  == largest i with cumw[i] <= xc
            const float* cw = &s_cumw[j * (K_ + 1)];
            int lo = 0, hi = K_ + 1;           // virtual cw[K+1] = +inf
            while (hi - lo > 1) {
                int mid = (lo + hi) >> 1;
                if (cw[mid] <= xc) lo = mid; else hi = mid;
            }
            const int idx = min(lo, K_ - 1);

            const float cwv = cw[idx];
            const float ibw = s_invbw[j * K_ + idx];
            const float ch  = s_ch   [j * K_ + idx];
            const float bh  = s_bh   [j * K_ + idx];
            const float dlt = s_delta[j * K_ + idx];
            const float d0  = s_dv[j * (K_ + 1) + idx];
            const float d1  = s_dv[j * (K_ + 1) + idx + 1];

            const float theta = (xc - cwv) * ibw;
            const float t1m   = theta * (1.0f - theta);
            const float denom = dlt + (d0 + d1 - 2.0f * dlt) * t1m;
            const float num   = bh * (dlt * theta * theta + d0 * t1m);
            y = ch + num / denom;

            const float omt = 1.0f - theta;
            const float A   = d1 * theta * theta + 2.0f * dlt * t1m + d0 * omt * omt;
            acc += __logf(dlt * dlt * A) - 2.0f * __logf(denom);
        }
        res[half] = y;
    }

    xout[base + lane]      = res[0];
    xout[base + lane + 32] = res[1];

    // warp-reduce logdet
#pragma unroll
    for (int o = 16; o; o >>= 1) acc += __shfl_xor_sync(0xffffffffu, acc, o);
    if (lane == 0) logd[row] = acc;
}

extern "C" void kernel_launch(void* const* d_in, const int* in_sizes, int n_in,
                              void* d_out, int out_size) {
    const float* u     = (const float*)d_in[0];
    const float* w     = (const float*)d_in[1];
    const float* h     = (const float*)d_in[2];
    const float* d     = (const float*)d_in[3];
    const int*   nodes = (const int*)  d_in[4];

    const int N = out_size - in_sizes[0];          // out = N*DTOT + N
    float* xout = (float*)d_out;
    float* logd = xout + (size_t)N * DTOT_;

    precompute_tables<<<1, 32>>>(w, h, d, nodes);
    const int rows_per_block = 8;                  // 256 threads / 32
    const int grid = (N + rows_per_block - 1) / rows_per_block;
    spline_kernel<<<grid, 256>>>(u, xout, logd, N);
}

// round 3
// speedup vs baseline: 1.2629x; 1.2629x over previous
#include <cuda_runtime.h>
#include <cuda_bf16.h>
#include <cstdint>

#define D_    32
#define K_    40
#define DTOT_ 64
#define B_    5.0f
#define LUTN_ 128

// Packed per-(dim,bin) tables. A has K_+1 entries/dim (pad cw=+huge sentinel).
__device__ float4 g_A[D_ * (K_ + 1)];   // {cumw, 1/bw, cumh, bh}
__device__ float4 g_Bt[D_ * K_];        // {delta, d0, d1, 0}
__device__ unsigned char g_lut[D_ * LUTN_];
__device__ int g_colmap[DTOT_];

__global__ void precompute_tables(const float* __restrict__ w,
                                  const float* __restrict__ h,
                                  const float* __restrict__ d,
                                  const int*   __restrict__ nodes) {
    int j = threadIdx.x;
    if (j == 0)
        for (int c = 0; c < DTOT_; c++) g_colmap[c] = -1;
    __syncthreads();
    if (j >= D_) return;
    g_colmap[nodes[j]] = j;

    float ew[K_], eh[K_];
    float cumw[K_ + 1], invbw[K_], ch[K_], bh[K_], dv[K_ + 1];
    // widths
    {
        float m = -1e30f;
        for (int i = 0; i < K_; i++) m = fmaxf(m, w[j * K_ + i]);
        float s = 0.f;
        for (int i = 0; i < K_; i++) { ew[i] = expf(w[j * K_ + i] - m); s += ew[i]; }
        float scl = (2.0f * B_) / s;
        float c = -B_;
        for (int i = 0; i < K_; i++) {
            cumw[i] = c;
            float bw = ew[i] * scl;
            invbw[i] = 1.0f / bw;
            c += bw;
        }
        cumw[K_] = c;
    }
    // heights
    {
        float m = -1e30f;
        for (int i = 0; i < K_; i++) m = fmaxf(m, h[j * K_ + i]);
        float s = 0.f;
        for (int i = 0; i < K_; i++) { eh[i] = expf(h[j * K_ + i] - m); s += eh[i]; }
        float scl = (2.0f * B_) / s;
        float c = -B_;
        for (int i = 0; i < K_; i++) {
            ch[i] = c;
            bh[i] = eh[i] * scl;
            c += bh[i];
        }
    }
    // derivatives
    dv[0] = 1.0f; dv[K_] = 1.0f;
    for (int i = 0; i < K_ - 1; i++) {
        float x = d[j * (K_ - 1) + i];
        dv[1 + i] = log1pf(expf(x));
    }
    // pack
    for (int i = 0; i < K_; i++) {
        g_A [j * (K_ + 1) + i] = make_float4(cumw[i], invbw[i], ch[i], bh[i]);
        g_Bt[j * K_ + i]       = make_float4(bh[i] * invbw[i], dv[i], dv[i + 1], 0.f);
    }
    g_A[j * (K_ + 1) + K_] = make_float4(1e30f, 0.f, 0.f, 0.f);  // sentinel
    // inverse-CDF LUT: bin containing each cell's left edge
    for (int m = 0; m < LUTN_; m++) {
        float xm = -B_ + (2.0f * B_) * ((float)m / (float)LUTN_);
        int idx = 0;
        while (idx < K_ - 1 && cumw[idx + 1] <= xm) idx++;
        g_lut[j * LUTN_ + m] = (unsigned char)idx;
    }
}

__global__ void __launch_bounds__(256)
spline_kernel(const float* __restrict__ u,
              float* __restrict__ xout,
              float* __restrict__ logd,
              int N) {
    __shared__ float4 s_A[D_ * (K_ + 1)];
    __shared__ float4 s_B[D_ * K_];
    __shared__ unsigned char s_lut[D_ * LUTN_];
    __shared__ int s_colmap[DTOT_];

    for (int i = threadIdx.x; i < D_ * (K_ + 1); i += blockDim.x) s_A[i] = g_A[i];
    for (int i = threadIdx.x; i < D_ * K_; i += blockDim.x)       s_B[i] = g_Bt[i];
    for (int i = threadIdx.x; i < D_ * LUTN_ / 4; i += blockDim.x)
        ((unsigned int*)s_lut)[i] = ((const unsigned int*)g_lut)[i];
    if (threadIdx.x < DTOT_) s_colmap[threadIdx.x] = g_colmap[threadIdx.x];
    __syncthreads();

    const int lane = threadIdx.x & 31;
    const int warp = threadIdx.x >> 5;

    // lane-constant dim mapping (hoisted out of the row loop)
    const int j0 = s_colmap[lane];
    const int j1 = s_colmap[lane + 32];
    const int jj[2]   = { j0, j1 };
    const int aBs[2]  = { j0 * (K_ + 1), j1 * (K_ + 1) };
    const int bBs[2]  = { j0 * K_,       j1 * K_ };
    const int lBs[2]  = { j0 * LUTN_,    j1 * LUTN_ };

    const int warps_total = gridDim.x * (256 / 32);
    const float inv_cell = (float)LUTN_ / (2.0f * B_);

    for (int row = blockIdx.x * 8 + warp; row < N; row += warps_total) {
        const size_t base = (size_t)row * DTOT_;
        float acc = 0.0f;
        float res[2];

#pragma unroll
        for (int half = 0; half < 2; half++) {
            const float x = u[base + lane + half * 32];
            float y = x;
            if (jj[half] >= 0 && fabsf(x) <= B_) {
                const float xc = fminf(fmaxf(x, -B_), B_);
                int m = (int)((xc + B_) * inv_cell);
                m = min(max(m, 0), LUTN_ - 1);
                int idx = (int)s_lut[lBs[half] + m];
                // two branchless corrections (right-closed semantics)
                idx += (xc >= s_A[aBs[half] + idx + 1].x);
                idx += (xc >= s_A[aBs[half] + idx + 1].x);

                const float4 A = s_A[aBs[half] + idx];
                const float4 Bv = s_B[bBs[half] + idx];
                const float theta = (xc - A.x) * A.y;
                const float t1m   = theta * (1.0f - theta);
                const float dlt = Bv.x, d0v = Bv.y, d1v = Bv.z;
                const float denom = dlt + (d0v + d1v - 2.0f * dlt) * t1m;
                const float rd = __fdividef(1.0f, denom);
                const float num = A.w * (dlt * theta * theta + d0v * t1m);
                y = A.z + num * rd;
                const float omt = 1.0f - theta;
                const float Aterm = d1v * theta * theta + 2.0f * dlt * t1m + d0v * omt * omt;
                acc += __logf(dlt * dlt * Aterm * rd * rd);
            }
            res[half] = y;
        }

        xout[base + lane]      = res[0];
        xout[base + lane + 32] = res[1];

#pragma unroll
        for (int o = 16; o; o >>= 1) acc += __shfl_xor_sync(0xffffffffu, acc, o);
        if (lane == 0) logd[row] = acc;
    }
}

extern "C" void kernel_launch(void* const* d_in, const int* in_sizes, int n_in,
                              void* d_out, int out_size) {
    const float* u     = (const float*)d_in[0];
    const float* w     = (const float*)d_in[1];
    const float* h     = (const float*)d_in[2];
    const float* d     = (const float*)d_in[3];
    const int*   nodes = (const int*)  d_in[4];

    const int N = out_size - in_sizes[0];
    float* xout = (float*)d_out;
    float* logd = xout + (size_t)N * DTOT_;

    precompute_tables<<<1, 32>>>(w, h, d, nodes);
    spline_kernel<<<1184, 256>>>(u, xout, logd, N);
}

// round 4
// speedup vs baseline: 2.9341x; 2.3232x over previous
#include <cuda_runtime.h>
#include <cstdint>

#define D_    32
#define K_    40
#define DTOT_ 64
#define Bb    5.0f
#define LUTN_ 128

__device__ float4 g_A   [D_ * K_];        // {cumw, 1/bw, cumh, bh}
__device__ float2 g_B2  [D_ * K_];        // {d0, d1}
__device__ float  g_edge[D_ * K_];        // cumw[i+1]
__device__ unsigned char g_lut[D_ * LUTN_];
__device__ int    g_colmap[DTOT_];

__global__ void precompute_tables(const float* __restrict__ w,
                                  const float* __restrict__ h,
                                  const float* __restrict__ d,
                                  const int*   __restrict__ nodes) {
    int j = threadIdx.x;
    if (j == 0)
        for (int c = 0; c < DTOT_; c++) g_colmap[c] = -1;
    __syncthreads();
    if (j >= D_) return;
    g_colmap[nodes[j]] = j;

    float ew[K_], eh[K_];
    float cumw[K_ + 1], invbw[K_], ch[K_], bh[K_], dv[K_ + 1];
    {
        float m = -1e30f;
        for (int i = 0; i < K_; i++) m = fmaxf(m, w[j * K_ + i]);
        float s = 0.f;
        for (int i = 0; i < K_; i++) { ew[i] = expf(w[j * K_ + i] - m); s += ew[i]; }
        float scl = (2.0f * Bb) / s;
        float c = -Bb;
        for (int i = 0; i < K_; i++) {
            cumw[i] = c;
            float bw = ew[i] * scl;
            invbw[i] = 1.0f / bw;
            c += bw;
        }
        cumw[K_] = c;
    }
    {
        float m = -1e30f;
        for (int i = 0; i < K_; i++) m = fmaxf(m, h[j * K_ + i]);
        float s = 0.f;
        for (int i = 0; i < K_; i++) { eh[i] = expf(h[j * K_ + i] - m); s += eh[i]; }
        float scl = (2.0f * Bb) / s;
        float c = -Bb;
        for (int i = 0; i < K_; i++) {
            ch[i] = c;
            bh[i] = eh[i] * scl;
            c += bh[i];
        }
    }
    dv[0] = 1.0f; dv[K_] = 1.0f;
    for (int i = 0; i < K_ - 1; i++)
        dv[1 + i] = log1pf(expf(d[j * (K_ - 1) + i]));

    for (int i = 0; i < K_; i++) {
        g_A   [j * K_ + i] = make_float4(cumw[i], invbw[i], ch[i], bh[i]);
        g_B2  [j * K_ + i] = make_float2(dv[i], dv[i + 1]);
        g_edge[j * K_ + i] = cumw[i + 1];
    }
    for (int m = 0; m < LUTN_; m++) {
        float xm = -Bb + (2.0f * Bb) * ((float)m / (float)LUTN_);
        int idx = 0;
        while (idx < K_ - 1 && cumw[idx + 1] <= xm) idx++;
        g_lut[j * LUTN_ + m] = (unsigned char)idx;
    }
}

// One spline-element evaluation (branchless tails). Table bases in smem.
__device__ __forceinline__ void eval_one(
    float x, int jvalid, int aB, int lB,
    const float4* s_A, const float2* s_B2, const float* s_edge,
    const unsigned char* s_lut, float inv_cell,
    float& y, float& acc)
{
    const float xc = fminf(fmaxf(x, -Bb), Bb);
    int m = min((int)((xc + Bb) * inv_cell), LUTN_ - 1);
    int idx = (int)s_lut[lB + m];
    idx += (xc >= s_edge[aB + idx]);
    idx = min(idx, K_ - 1);

    const float4 A  = s_A [aB + idx];
    const float2 Bv = s_B2[aB + idx];
    const float ibw = A.y, bh = A.w;
    const float dlt = bh * ibw;
    const float theta = (xc - A.x) * ibw;
    const float t2  = theta * theta;
    const float t1m = theta - t2;
    const float d0v = Bv.x, d1v = Bv.y;
    const float denom = fmaf(d0v + d1v - 2.0f * dlt, t1m, dlt);
    const float rd  = __fdividef(1.0f, denom);
    const float num = bh * fmaf(dlt, t2, d0v * t1m);
    const float ys  = A.z + num * rd;
    const float omt = 1.0f - theta;
    const float At  = d1v * t2 + 2.0f * dlt * t1m + d0v * omt * omt;
    const float ld  = __logf(dlt * dlt * At * rd * rd);

    const bool valid = (jvalid >= 0) && (fabsf(x) <= Bb);
    y = valid ? ys : x;
    acc += valid ? ld : 0.0f;
}

__global__ void __launch_bounds__(512)
spline_kernel(const float* __restrict__ u,
              float* __restrict__ xout,
              float* __restrict__ logd,
              int N) {
    __shared__ float4 s_A[D_ * K_];
    __shared__ float2 s_B2[D_ * K_];
    __shared__ float  s_edge[D_ * K_];
    __shared__ unsigned char s_lut[D_ * LUTN_];
    __shared__ int s_colmap[DTOT_];

    for (int i = threadIdx.x; i < D_ * K_; i += blockDim.x) {
        s_A[i]    = g_A[i];
        s_B2[i]   = g_B2[i];
        s_edge[i] = g_edge[i];
    }
    for (int i = threadIdx.x; i < D_ * LUTN_ / 4; i += blockDim.x)
        ((unsigned int*)s_lut)[i] = ((const unsigned int*)g_lut)[i];
    if (threadIdx.x < DTOT_) s_colmap[threadIdx.x] = g_colmap[threadIdx.x];
    __syncthreads();

    const int lane = threadIdx.x & 31;
    const int warp = threadIdx.x >> 5;
    const int wpb  = blockDim.x >> 5;

    const int j0 = s_colmap[lane];
    const int j1 = s_colmap[lane + 32];
    const int aB0 = max(j0, 0) * K_;
    const int aB1 = max(j1, 0) * K_;
    const int lB0 = max(j0, 0) * LUTN_;
    const int lB1 = max(j1, 0) * LUTN_;
    const unsigned full = 0xffffffffu;
    const bool any0 = __any_sync(full, j0 >= 0);
    const bool any1 = __any_sync(full, j1 >= 0);
    const float inv_cell = (float)LUTN_ / (2.0f * Bb);

    const int stride = gridDim.x * wpb * 2;

    for (int row = (blockIdx.x * wpb + warp) * 2; row < N; row += stride) {
        const int  rowb  = row + 1;
        const bool haveb = rowb < N;
        const size_t ba = (size_t)row  * DTOT_;
        const size_t bb = (size_t)rowb * DTOT_;

        // Issue all loads first (ILP across the two rows).
        const float xa0 = u[ba + lane];
        const float xa1 = u[ba + lane + 32];
        const float xb0 = haveb ? u[bb + lane] : 0.0f;
        const float xb1 = haveb ? u[bb + lane + 32] : 0.0f;

        float acca = 0.0f, accb = 0.0f;
        float ya0 = xa0, ya1 = xa1, yb0 = xb0, yb1 = xb1;

        if (any0) {
            eval_one(xa0, j0, aB0, lB0, s_A, s_B2, s_edge, s_lut, inv_cell, ya0, acca);
            eval_one(xb0, j0, aB0, lB0, s_A, s_B2, s_edge, s_lut, inv_cell, yb0, accb);
        }
        if (any1) {
            eval_one(xa1, j1, aB1, lB1, s_A, s_B2, s_edge, s_lut, inv_cell, ya1, acca);
            eval_one(xb1, j1, aB1, lB1, s_A, s_B2, s_edge, s_lut, inv_cell, yb1, accb);
        }

        xout[ba + lane]      = ya0;
        xout[ba + lane + 32] = ya1;
        if (haveb) {
            xout[bb + lane]      = yb0;
            xout[bb + lane + 32] = yb1;
        }

#pragma unroll
        for (int o = 16; o; o >>= 1) {
            acca += __shfl_xor_sync(full, acca, o);
            accb += __shfl_xor_sync(full, accb, o);
        }
        if (lane == 0) {
            logd[row] = acca;
            if (haveb) logd[rowb] = accb;
        }
    }
}

extern "C" void kernel_launch(void* const* d_in, const int* in_sizes, int n_in,
                              void* d_out, int out_size) {
    const float* u     = (const float*)d_in[0];
    const float* w     = (const float*)d_in[1];
    const float* h     = (const float*)d_in[2];
    const float* d     = (const float*)d_in[3];
    const int*   nodes = (const int*)  d_in[4];

    const int N = out_size - in_sizes[0];
    float* xout = (float*)d_out;
    float* logd = xout + (size_t)N * DTOT_;

    precompute_tables<<<1, 32>>>(w, h, d, nodes);
    spline_kernel<<<592, 512>>>(u, xout, logd, N);
}

// round 6
// speedup vs baseline: 3.8105x; 1.2987x over previous
#include <cuda_runtime.h>
#include <cstdint>

#define D_      32
#define K_      40
#define STRIDE_ 41      // padded: breaks stride%32-words == 0 bank alignment
#define DTOT_   64
#define Bb      5.0f
#define LUTN_   128
#define LUTS_   132     // padded LUT byte stride

__device__ float4 g_A   [D_ * STRIDE_];   // {cumw, 1/bw, cumh, bh}
__device__ float2 g_B2  [D_ * STRIDE_];   // {d0, d1}
__device__ float  g_edge[D_ * STRIDE_];   // cumw[i+1]
__device__ unsigned char g_lut[D_ * LUTS_];
__device__ int    g_colmap[DTOT_];

#define FULLM 0xffffffffu
__device__ __forceinline__ float warp_max(float v) {
#pragma unroll
    for (int o = 16; o; o >>= 1) v = fmaxf(v, __shfl_xor_sync(FULLM, v, o));
    return v;
}
__device__ __forceinline__ float warp_sum(float v) {
#pragma unroll
    for (int o = 16; o; o >>= 1) v += __shfl_xor_sync(FULLM, v, o);
    return v;
}
__device__ __forceinline__ float warp_scan(float v, int lane) {
#pragma unroll
    for (int o = 1; o < 32; o <<= 1) {
        float t = __shfl_up_sync(FULLM, v, o);
        if (lane >= o) v += t;
    }
    return v;
}

// Warp-per-dim precompute: 32 warps, ~2us.
__global__ void __launch_bounds__(1024)
precompute_tables(const float* __restrict__ w,
                  const float* __restrict__ h,
                  const float* __restrict__ d,
                  const int*   __restrict__ nodes) {
    __shared__ float scumw[D_][K_ + 1];
    const int tid = threadIdx.x, lane = tid & 31, j = tid >> 5;

    if (tid < DTOT_) g_colmap[tid] = -1;
    __syncthreads();
    if (tid < D_) g_colmap[nodes[tid]] = tid;

    // ---- widths: softmax * 2B, prefix for cumw ----
    const float w0 = w[j * K_ + lane];
    const float w1 = (lane < 8) ? w[j * K_ + 32 + lane] : -1e30f;
    float m = warp_max(fmaxf(w0, w1));
    const float e0 = expf(w0 - m);
    const float e1 = (lane < 8) ? expf(w1 - m) : 0.0f;
    const float scl = (2.0f * Bb) / warp_sum(e0 + e1);
    const float bw0 = e0 * scl, bw1 = e1 * scl;
    float s0 = warp_scan(bw0, lane);
    const float tot0 = __shfl_sync(FULLM, s0, 31);
    float s1 = warp_scan(bw1, lane) + tot0;
    const float cw0 = -Bb + s0 - bw0, cw0n = -Bb + s0;
    const float cw1 = -Bb + s1 - bw1, cw1n = -Bb + s1;

    // ---- heights ----
    const float h0 = h[j * K_ + lane];
    const float h1 = (lane < 8) ? h[j * K_ + 32 + lane] : -1e30f;
    m = warp_max(fmaxf(h0, h1));
    const float f0 = expf(h0 - m);
    const float f1 = (lane < 8) ? expf(h1 - m) : 0.0f;
    const float scl2 = (2.0f * Bb) / warp_sum(f0 + f1);
    const float bh0 = f0 * scl2, bh1 = f1 * scl2;
    float t0 = warp_scan(bh0, lane);
    const float htot0 = __shfl_sync(FULLM, t0, 31);
    float t1 = warp_scan(bh1, lane) + htot0;
    const float ch0 = -Bb + t0 - bh0;
    const float ch1 = -Bb + t1 - bh1;

    // ---- derivatives: dv(i) = (i==0||i==K)?1:softplus(d[i-1]) ----
    const float dva0 = (lane == 0) ? 1.0f : log1pf(expf(d[j * (K_ - 1) + lane - 1]));
    const float dvb0 = log1pf(expf(d[j * (K_ - 1) + lane]));   // i+1 in 1..32, interior
    float dva1 = 0.f, dvb1 = 0.f;
    if (lane < 8) {
        const int i = 32 + lane;
        dva1 = log1pf(expf(d[j * (K_ - 1) + i - 1]));
        dvb1 = (i + 1 == K_) ? 1.0f : log1pf(expf(d[j * (K_ - 1) + i]));
    }

    // ---- store tables ----
    {
        const int b = j * STRIDE_ + lane;
        g_A[b]    = make_float4(cw0, 1.0f / bw0, ch0, bh0);
        g_B2[b]   = make_float2(dva0, dvb0);
        g_edge[b] = cw0n;
        scumw[j][lane] = cw0;
    }
    if (lane < 8) {
        const int i = 32 + lane;
        const int b = j * STRIDE_ + i;
        g_A[b]    = make_float4(cw1, 1.0f / bw1, ch1, bh1);
        g_B2[b]   = make_float2(dva1, dvb1);
        g_edge[b] = cw1n;
        scumw[j][i] = cw1;
        if (i == K_ - 1) scumw[j][K_] = cw1n;
    }
    __syncwarp();

    // ---- LUT: 4 cells/lane, binary search over cumw[0..39] ----
#pragma unroll
    for (int c = 0; c < 4; c++) {
        const int mm = lane * 4 + c;
        const float xm = -Bb + (2.0f * Bb) * ((float)mm / (float)LUTN_);
        int lo = 0, hi = K_;
        while (hi - lo > 1) {
            const int mid = (lo + hi) >> 1;
            if (scumw[j][mid] <= xm) lo = mid; else hi = mid;
        }
        g_lut[j * LUTS_ + mm] = (unsigned char)lo;
    }
}

__device__ __forceinline__ void eval_one(
    float x, int jvalid, int aB, int lB,
    const float4* s_A, const float2* s_B2, const float* s_edge,
    const unsigned char* s_lut, float inv_cell,
    float& y, float& acc)
{
    const float xc = fminf(fmaxf(x, -Bb), Bb);
    int m = min((int)((xc + Bb) * inv_cell), LUTN_ - 1);
    int idx = (int)s_lut[lB + m];
    idx += (xc >= s_edge[aB + idx]);
    idx = min(idx, K_ - 1);

    const float4 A  = s_A [aB + idx];
    const float2 Bv = s_B2[aB + idx];
    const float ibw = A.y, bh = A.w;
    const float dlt = bh * ibw;
    const float theta = (xc - A.x) * ibw;
    const float t2  = theta * theta;
    const float t1m = theta - t2;
    const float d0v = Bv.x, d1v = Bv.y;
    const float denom = fmaf(d0v + d1v - 2.0f * dlt, t1m, dlt);
    const float rd  = __fdividef(1.0f, denom);
    const float num = bh * fmaf(dlt, t2, d0v * t1m);
    const float ys  = A.z + num * rd;
    const float omt = 1.0f - theta;
    const float At  = d1v * t2 + 2.0f * dlt * t1m + d0v * omt * omt;
    const float ld  = __logf(dlt * dlt * At * rd * rd);

    const bool valid = (jvalid >= 0) && (fabsf(x) <= Bb);
    y = valid ? ys : x;
    acc += valid ? ld : 0.0f;
}

__global__ void __launch_bounds__(512)
spline_kernel(const float* __restrict__ u,
              float* __restrict__ xout,
              float* __restrict__ logd,
              int N) {
    __shared__ float4 s_A[D_ * STRIDE_];
    __shared__ float2 s_B2[D_ * STRIDE_];
    __shared__ float  s_edge[D_ * STRIDE_];
    __shared__ unsigned char s_lut[D_ * LUTS_];
    __shared__ int s_colmap[DTOT_];

    for (int i = threadIdx.x; i < D_ * STRIDE_; i += blockDim.x) {
        s_A[i]    = g_A[i];
        s_B2[i]   = g_B2[i];
        s_edge[i] = g_edge[i];
    }
    for (int i = threadIdx.x; i < D_ * LUTS_ / 4; i += blockDim.x)
        ((unsigned int*)s_lut)[i] = ((const unsigned int*)g_lut)[i];
    if (threadIdx.x < DTOT_) s_colmap[threadIdx.x] = g_colmap[threadIdx.x];
    __syncthreads();

    const int lane = threadIdx.x & 31;
    const int warp = threadIdx.x >> 5;
    const int wpb  = blockDim.x >> 5;

    const int j0 = s_colmap[lane];
    const int j1 = s_colmap[lane + 32];
    const int aB0 = max(j0, 0) * STRIDE_;
    const int aB1 = max(j1, 0) * STRIDE_;
    const int lB0 = max(j0, 0) * LUTS_;
    const int lB1 = max(j1, 0) * LUTS_;
    const bool any0 = __any_sync(FULLM, j0 >= 0);
    const bool any1 = __any_sync(FULLM, j1 >= 0);
    const float inv_cell = (float)LUTN_ / (2.0f * Bb);

    const int stride = gridDim.x * wpb * 2;

    for (int row = (blockIdx.x * wpb + warp) * 2; row < N; row += stride) {
        const int  rowb  = row + 1;
        const bool haveb = rowb < N;
        const size_t ba = (size_t)row  * DTOT_;
        const size_t bb = (size_t)rowb * DTOT_;

        const float xa0 = u[ba + lane];
        const float xa1 = u[ba + lane + 32];
        const float xb0 = haveb ? u[bb + lane] : 0.0f;
        const float xb1 = haveb ? u[bb + lane + 32] : 0.0f;

        float acca = 0.0f, accb = 0.0f;
        float ya0 = xa0, ya1 = xa1, yb0 = xb0, yb1 = xb1;

        if (any0) {
            eval_one(xa0, j0, aB0, lB0, s_A, s_B2, s_edge, s_lut, inv_cell, ya0, acca);
            eval_one(xb0, j0, aB0, lB0, s_A, s_B2, s_edge, s_lut, inv_cell, yb0, accb);
        }
        if (any1) {
            eval_one(xa1, j1, aB1, lB1, s_A, s_B2, s_edge, s_lut, inv_cell, ya1, acca);
            eval_one(xb1, j1, aB1, lB1, s_A, s_B2, s_edge, s_lut, inv_cell, yb1, accb);
        }

        xout[ba + lane]      = ya0;
        xout[ba + lane + 32] = ya1;
        if (haveb) {
            xout[bb + lane]      = yb0;
            xout[bb + lane + 32] = yb1;
        }

#pragma unroll
        for (int o = 16; o; o >>= 1) {
            acca += __shfl_xor_sync(FULLM, acca, o);
            accb += __shfl_xor_sync(FULLM, accb, o);
        }
        if (lane == 0) {
            logd[row] = acca;
            if (haveb) logd[rowb] = accb;
        }
    }
}

extern "C" void kernel_launch(void* const* d_in, const int* in_sizes, int n_in,
                              void* d_out, int out_size) {
    const float* u     = (const float*)d_in[0];
    const float* w     = (const float*)d_in[1];
    const float* h     = (const float*)d_in[2];
    const float* d     = (const float*)d_in[3];
    const int*   nodes = (const int*)  d_in[4];

    const int N = out_size - in_sizes[0];
    float* xout = (float*)d_out;
    float* logd = xout + (size_t)N * DTOT_;

    precompute_tables<<<1, 1024>>>(w, h, d, nodes);
    spline_kernel<<<592, 512>>>(u, xout, logd, N);
}

// round 7
// speedup vs baseline: 4.0921x; 1.0739x over previous
#include <cuda_runtime.h>
#include <cstdint>

#define D_      32
#define K_      40
#define STRIDE_ 41       // padded table stride (entries)
#define DTOT_   64
#define Bb      5.0f
#define LUTN_   128
#define LUTS_   132      // padded LUT stride (entries)

__device__ float4   g_A  [D_ * STRIDE_];  // {cumw, 1/bw, cumh, bh}
__device__ float2   g_B2 [D_ * STRIDE_];  // {d0, d1}
__device__ unsigned g_lutp[D_ * LUTS_];   // fp32 edge with idx in low 6 mantissa bits
__device__ int      g_colmap[DTOT_];

#define FULLM 0xffffffffu
__device__ __forceinline__ float warp_max(float v) {
#pragma unroll
    for (int o = 16; o; o >>= 1) v = fmaxf(v, __shfl_xor_sync(FULLM, v, o));
    return v;
}
__device__ __forceinline__ float warp_sum(float v) {
#pragma unroll
    for (int o = 16; o; o >>= 1) v += __shfl_xor_sync(FULLM, v, o);
    return v;
}
__device__ __forceinline__ float warp_scan(float v, int lane) {
#pragma unroll
    for (int o = 1; o < 32; o <<= 1) {
        float t = __shfl_up_sync(FULLM, v, o);
        if (lane >= o) v += t;
    }
    return v;
}

// Warp-per-dim precompute (32 warps).
__global__ void __launch_bounds__(1024)
precompute_tables(const float* __restrict__ w,
                  const float* __restrict__ h,
                  const float* __restrict__ d,
                  const int*   __restrict__ nodes) {
    __shared__ float scumw[D_][K_ + 1];
    const int tid = threadIdx.x, lane = tid & 31, j = tid >> 5;

    if (tid < DTOT_) g_colmap[tid] = -1;
    __syncthreads();
    if (tid < D_) g_colmap[nodes[tid]] = tid;

    // widths
    const float w0 = w[j * K_ + lane];
    const float w1 = (lane < 8) ? w[j * K_ + 32 + lane] : -1e30f;
    float m = warp_max(fmaxf(w0, w1));
    const float e0 = expf(w0 - m);
    const float e1 = (lane < 8) ? expf(w1 - m) : 0.0f;
    const float scl = (2.0f * Bb) / warp_sum(e0 + e1);
    const float bw0 = e0 * scl, bw1 = e1 * scl;
    float s0 = warp_scan(bw0, lane);
    const float tot0 = __shfl_sync(FULLM, s0, 31);
    float s1 = warp_scan(bw1, lane) + tot0;
    const float cw0 = -Bb + s0 - bw0, cw0n = -Bb + s0;
    const float cw1 = -Bb + s1 - bw1, cw1n = -Bb + s1;

    // heights
    const float h0 = h[j * K_ + lane];
    const float h1 = (lane < 8) ? h[j * K_ + 32 + lane] : -1e30f;
    m = warp_max(fmaxf(h0, h1));
    const float f0 = expf(h0 - m);
    const float f1 = (lane < 8) ? expf(h1 - m) : 0.0f;
    const float scl2 = (2.0f * Bb) / warp_sum(f0 + f1);
    const float bh0 = f0 * scl2, bh1 = f1 * scl2;
    float t0 = warp_scan(bh0, lane);
    const float htot0 = __shfl_sync(FULLM, t0, 31);
    float t1 = warp_scan(bh1, lane) + htot0;
    const float ch0 = -Bb + t0 - bh0;
    const float ch1 = -Bb + t1 - bh1;

    // derivatives dv(i) = (i==0||i==K)?1:softplus(d[i-1])
    const float dva0 = (lane == 0) ? 1.0f : log1pf(expf(d[j * (K_ - 1) + lane - 1]));
    const float dvb0 = log1pf(expf(d[j * (K_ - 1) + lane]));
    float dva1 = 0.f, dvb1 = 0.f;
    if (lane < 8) {
        const int i = 32 + lane;
        dva1 = log1pf(expf(d[j * (K_ - 1) + i - 1]));
        dvb1 = (i + 1 == K_) ? 1.0f : log1pf(expf(d[j * (K_ - 1) + i]));
    }

    {
        const int b = j * STRIDE_ + lane;
        g_A[b]  = make_float4(cw0, 1.0f / bw0, ch0, bh0);
        g_B2[b] = make_float2(dva0, dvb0);
        scumw[j][lane] = cw0;
    }
    if (lane < 8) {
        const int i = 32 + lane;
        const int b = j * STRIDE_ + i;
        g_A[b]  = make_float4(cw1, 1.0f / bw1, ch1, bh1);
        g_B2[b] = make_float2(dva1, dvb1);
        scumw[j][i] = cw1;
        if (i == K_ - 1) scumw[j][K_] = cw1n;
    }
    __syncwarp();

    // LUT: 4 cells/lane; entry = fp32(cumw[idx+1]) with idx in low 6 mantissa bits
#pragma unroll
    for (int c = 0; c < 4; c++) {
        const int mm = lane * 4 + c;
        const float xm = -Bb + (2.0f * Bb) * ((float)mm / (float)LUTN_);
        int lo = 0, hi = K_;
        while (hi - lo > 1) {
            const int mid = (lo + hi) >> 1;
            if (scumw[j][mid] <= xm) lo = mid; else hi = mid;
        }
        const float edge = scumw[j][lo + 1];
        unsigned bits = (__float_as_uint(edge) & ~63u) | (unsigned)lo;
        g_lutp[j * LUTS_ + mm] = bits;
    }
}

__device__ __forceinline__ void eval_one(
    float x, int jvalid, int aB, int lB,
    const float4* s_A, const float2* s_B2, const unsigned* s_lutp,
    float& y, float& acc)
{
    const float xc = fminf(fmaxf(x, -Bb), Bb);
    int m = (int)fmaf(xc, (float)LUTN_ / (2.0f * Bb), (float)(LUTN_ / 2));
    m = min(m, LUTN_ - 1);
    const unsigned e = s_lutp[lB + m];
    int idx = (int)(e & 63u);
    const float edge = __uint_as_float(e & ~63u);
    idx += (xc >= edge);
    idx = min(idx, K_ - 1);

    const float4 A  = s_A [aB + idx];
    const float2 Bv = s_B2[aB + idx];
    const float ibw = A.y, bh = A.w;
    const float dlt = bh * ibw;
    const float theta = (xc - A.x) * ibw;
    const float t2  = theta * theta;
    const float t1m = theta - t2;
    const float d0v = Bv.x, d1v = Bv.y;
    const float denom = fmaf(d0v + d1v - 2.0f * dlt, t1m, dlt);
    const float rd  = __fdividef(1.0f, denom);
    const float num = bh * fmaf(dlt, t2, d0v * t1m);
    const float ys  = A.z + num * rd;
    const float omt = 1.0f - theta;
    const float At  = d1v * t2 + 2.0f * dlt * t1m + d0v * omt * omt;
    const float ld  = __logf(dlt * dlt * At * rd * rd);

    const bool valid = (jvalid >= 0) && (fabsf(x) <= Bb);
    y = valid ? ys : x;
    acc += valid ? ld : 0.0f;
}

// Dynamic smem layout (16-B aligned first): A, B2, lutp, colmap
#define SM_A_ELE   (D_ * STRIDE_)
#define SM_B_OFF   (SM_A_ELE * 16)
#define SM_L_OFF   (SM_B_OFF + SM_A_ELE * 8)
#define SM_C_OFF   (SM_L_OFF + D_ * LUTS_ * 4)
#define SM_TOTAL   (SM_C_OFF + DTOT_ * 4)

extern __shared__ unsigned char smem_raw[];

__global__ void __launch_bounds__(512)
spline_kernel(const float* __restrict__ u,
              float* __restrict__ xout,
              float* __restrict__ logd,
              int N) {
    float4*   s_A    = (float4*)smem_raw;
    float2*   s_B2   = (float2*)(smem_raw + SM_B_OFF);
    unsigned* s_lutp = (unsigned*)(smem_raw + SM_L_OFF);
    int*      s_colmap = (int*)(smem_raw + SM_C_OFF);

    for (int i = threadIdx.x; i < SM_A_ELE; i += blockDim.x) {
        s_A[i]  = g_A[i];
        s_B2[i] = g_B2[i];
    }
    for (int i = threadIdx.x; i < D_ * LUTS_; i += blockDim.x)
        s_lutp[i] = g_lutp[i];
    if (threadIdx.x < DTOT_) s_colmap[threadIdx.x] = g_colmap[threadIdx.x];
    __syncthreads();

    const int lane = threadIdx.x & 31;
    const int warp = threadIdx.x >> 5;
    const int wpb  = blockDim.x >> 5;

    const int j0 = s_colmap[lane];
    const int j1 = s_colmap[lane + 32];
    const int aB0 = max(j0, 0) * STRIDE_;
    const int aB1 = max(j1, 0) * STRIDE_;
    const int lB0 = max(j0, 0) * LUTS_;
    const int lB1 = max(j1, 0) * LUTS_;
    const bool any0 = __any_sync(FULLM, j0 >= 0);
    const bool any1 = __any_sync(FULLM, j1 >= 0);

    const int stride = gridDim.x * wpb * 2;

    for (int row = (blockIdx.x * wpb + warp) * 2; row < N; row += stride) {
        const int  rowb  = row + 1;
        const bool haveb = rowb < N;
        const size_t ba = (size_t)row  * DTOT_;
        const size_t bb = (size_t)rowb * DTOT_;

        const float xa0 = u[ba + lane];
        const float xa1 = u[ba + lane + 32];
        const float xb0 = haveb ? u[bb + lane] : 0.0f;
        const float xb1 = haveb ? u[bb + lane + 32] : 0.0f;

        float acca = 0.0f, accb = 0.0f;
        float ya0 = xa0, ya1 = xa1, yb0 = xb0, yb1 = xb1;

        if (any0) {
            eval_one(xa0, j0, aB0, lB0, s_A, s_B2, s_lutp, ya0, acca);
            eval_one(xb0, j0, aB0, lB0, s_A, s_B2, s_lutp, yb0, accb);
        }
        if (any1) {
            eval_one(xa1, j1, aB1, lB1, s_A, s_B2, s_lutp, ya1, acca);
            eval_one(xb1, j1, aB1, lB1, s_A, s_B2, s_lutp, yb1, accb);
        }

        xout[ba + lane]      = ya0;
        xout[ba + lane + 32] = ya1;
        if (haveb) {
            xout[bb + lane]      = yb0;
            xout[bb + lane + 32] = yb1;
        }

#pragma unroll
        for (int o = 16; o; o >>= 1) {
            acca += __shfl_xor_sync(FULLM, acca, o);
            accb += __shfl_xor_sync(FULLM, accb, o);
        }
        if (lane == 0) {
            logd[row] = acca;
            if (haveb) logd[rowb] = accb;
        }
    }
}

extern "C" void kernel_launch(void* const* d_in, const int* in_sizes, int n_in,
                              void* d_out, int out_size) {
    const float* u     = (const float*)d_in[0];
    const float* w     = (const float*)d_in[1];
    const float* h     = (const float*)d_in[2];
    const float* d     = (const float*)d_in[3];
    const int*   nodes = (const int*)  d_in[4];

    const int N = out_size - in_sizes[0];
    float* xout = (float*)d_out;
    float* logd = xout + (size_t)N * DTOT_;

    static int smem_set = 0;
    if (!smem_set) {
        cudaFuncSetAttribute(spline_kernel,
                             cudaFuncAttributeMaxDynamicSharedMemorySize, SM_TOTAL);
        smem_set = 1;
    }

    precompute_tables<<<1, 1024>>>(w, h, d, nodes);
    spline_kernel<<<592, 512, SM_TOTAL>>>(u, xout, logd, N);
}

// round 8
// speedup vs baseline: 4.1800x; 1.0215x over previous
#include <cuda_runtime.h>
#include <cstdint>

#define D_      32
#define K_      40
#define DTOT_   64
#define Bb      5.0f
#define LUTN_   128

// Transposed tables: [bin][dim] — bank depends only on dim, conflict-free gathers.
__device__ float4   g_At  [K_ * D_];     // {cumw, 1/bw, cumh, bh}
__device__ float2   g_B2t [K_ * D_];     // {d0, d1}
__device__ unsigned g_lutp[LUTN_ * D_];  // fp32 edge, idx in low 6 mantissa bits
__device__ int      g_colmap[DTOT_];

#define FULLM 0xffffffffu
__device__ __forceinline__ float warp_max(float v) {
#pragma unroll
    for (int o = 16; o; o >>= 1) v = fmaxf(v, __shfl_xor_sync(FULLM, v, o));
    return v;
}
__device__ __forceinline__ float warp_sum(float v) {
#pragma unroll
    for (int o = 16; o; o >>= 1) v += __shfl_xor_sync(FULLM, v, o);
    return v;
}
__device__ __forceinline__ float warp_scan(float v, int lane) {
#pragma unroll
    for (int o = 1; o < 32; o <<= 1) {
        float t = __shfl_up_sync(FULLM, v, o);
        if (lane >= o) v += t;
    }
    return v;
}

// Warp-per-dim precompute (32 warps).
__global__ void __launch_bounds__(1024)
precompute_tables(const float* __restrict__ w,
                  const float* __restrict__ h,
                  const float* __restrict__ d,
                  const int*   __restrict__ nodes) {
    __shared__ float scumw[D_][K_ + 1];
    const int tid = threadIdx.x, lane = tid & 31, j = tid >> 5;

    if (tid < DTOT_) g_colmap[tid] = -1;
    __syncthreads();
    if (tid < D_) g_colmap[nodes[tid]] = tid;

    // widths
    const float w0 = w[j * K_ + lane];
    const float w1 = (lane < 8) ? w[j * K_ + 32 + lane] : -1e30f;
    float m = warp_max(fmaxf(w0, w1));
    const float e0 = expf(w0 - m);
    const float e1 = (lane < 8) ? expf(w1 - m) : 0.0f;
    const float scl = (2.0f * Bb) / warp_sum(e0 + e1);
    const float bw0 = e0 * scl, bw1 = e1 * scl;
    float s0 = warp_scan(bw0, lane);
    const float tot0 = __shfl_sync(FULLM, s0, 31);
    float s1 = warp_scan(bw1, lane) + tot0;
    const float cw0 = -Bb + s0 - bw0, cw0n = -Bb + s0;
    const float cw1 = -Bb + s1 - bw1, cw1n = -Bb + s1;

    // heights
    const float h0 = h[j * K_ + lane];
    const float h1 = (lane < 8) ? h[j * K_ + 32 + lane] : -1e30f;
    m = warp_max(fmaxf(h0, h1));
    const float f0 = expf(h0 - m);
    const float f1 = (lane < 8) ? expf(h1 - m) : 0.0f;
    const float scl2 = (2.0f * Bb) / warp_sum(f0 + f1);
    const float bh0 = f0 * scl2, bh1 = f1 * scl2;
    float t0 = warp_scan(bh0, lane);
    const float htot0 = __shfl_sync(FULLM, t0, 31);
    float t1 = warp_scan(bh1, lane) + htot0;
    const float ch0 = -Bb + t0 - bh0;
    const float ch1 = -Bb + t1 - bh1;

    // derivatives dv(i) = (i==0||i==K)?1:softplus(d[i-1])
    const float dva0 = (lane == 0) ? 1.0f : log1pf(expf(d[j * (K_ - 1) + lane - 1]));
    const float dvb0 = log1pf(expf(d[j * (K_ - 1) + lane]));
    float dva1 = 0.f, dvb1 = 0.f;
    if (lane < 8) {
        const int i = 32 + lane;
        dva1 = log1pf(expf(d[j * (K_ - 1) + i - 1]));
        dvb1 = (i + 1 == K_) ? 1.0f : log1pf(expf(d[j * (K_ - 1) + i]));
    }

    // transposed stores: [bin][dim]
    {
        g_At [lane * D_ + j] = make_float4(cw0, 1.0f / bw0, ch0, bh0);
        g_B2t[lane * D_ + j] = make_float2(dva0, dvb0);
        scumw[j][lane] = cw0;
    }
    if (lane < 8) {
        const int i = 32 + lane;
        g_At [i * D_ + j] = make_float4(cw1, 1.0f / bw1, ch1, bh1);
        g_B2t[i * D_ + j] = make_float2(dva1, dvb1);
        scumw[j][i] = cw1;
        if (i == K_ - 1) scumw[j][K_] = cw1n;
    }
    __syncwarp();

    // LUT (transposed): entry[m][j] = fp32(cumw[idx+1]) | idx (low 6 bits)
#pragma unroll
    for (int c = 0; c < 4; c++) {
        const int mm = lane * 4 + c;
        const float xm = -Bb + (2.0f * Bb) * ((float)mm / (float)LUTN_);
        int lo = 0, hi = K_;
        while (hi - lo > 1) {
            const int mid = (lo + hi) >> 1;
            if (scumw[j][mid] <= xm) lo = mid; else hi = mid;
        }
        const float edge = scumw[j][lo + 1];
        g_lutp[mm * D_ + j] = (__float_as_uint(edge) & ~63u) | (unsigned)lo;
    }
}

__device__ __forceinline__ void eval_one(
    float x, int jvalid, int jb,
    const float4* s_A, const float2* s_B2, const unsigned* s_lutp,
    float& y, float& acc)
{
    const float xc = fminf(fmaxf(x, -Bb), Bb);
    int m = (int)fmaf(xc, (float)LUTN_ / (2.0f * Bb), (float)(LUTN_ / 2));
    m = min(m, LUTN_ - 1);
    const unsigned e = s_lutp[m * D_ + jb];
    int idx = (int)(e & 63u);
    const float edge = __uint_as_float(e & ~63u);
    idx += (xc >= edge);
    idx = min(idx, K_ - 1);

    const float4 A  = s_A [idx * D_ + jb];
    const float2 Bv = s_B2[idx * D_ + jb];
    const float ibw = A.y, bh = A.w;
    const float dlt = bh * ibw;
    const float theta = (xc - A.x) * ibw;
    const float t2  = theta * theta;
    const float t1m = theta - t2;
    const float d0v = Bv.x, d1v = Bv.y;
    const float denom = fmaf(d0v + d1v - 2.0f * dlt, t1m, dlt);
    const float rd  = __fdividef(1.0f, denom);
    const float num = bh * fmaf(dlt, t2, d0v * t1m);
    const float ys  = A.z + num * rd;
    const float omt = 1.0f - theta;
    const float At  = d1v * t2 + 2.0f * dlt * t1m + d0v * omt * omt;
    const float ld  = __logf(dlt * dlt * At * rd * rd);

    const bool valid = (jvalid >= 0) && (fabsf(x) <= Bb);
    y = valid ? ys : x;
    acc += valid ? ld : 0.0f;
}

// Dynamic smem layout: A(20480) B2(10240) lut(16384) colmap(256)
#define SM_A_ELE  (K_ * D_)
#define SM_B_OFF  (SM_A_ELE * 16)
#define SM_L_OFF  (SM_B_OFF + SM_A_ELE * 8)
#define SM_C_OFF  (SM_L_OFF + LUTN_ * D_ * 4)
#define SM_TOTAL  (SM_C_OFF + DTOT_ * 4)

extern __shared__ unsigned char smem_raw[];

__global__ void __launch_bounds__(512)
spline_kernel(const float* __restrict__ u,
              float* __restrict__ xout,
              float* __restrict__ logd,
              int N) {
    float4*   s_A      = (float4*)smem_raw;
    float2*   s_B2     = (float2*)(smem_raw + SM_B_OFF);
    unsigned* s_lutp   = (unsigned*)(smem_raw + SM_L_OFF);
    int*      s_colmap = (int*)(smem_raw + SM_C_OFF);

    for (int i = threadIdx.x; i < SM_A_ELE; i += blockDim.x) {
        s_A[i]  = g_At[i];
        s_B2[i] = g_B2t[i];
    }
    for (int i = threadIdx.x; i < LUTN_ * D_; i += blockDim.x)
        s_lutp[i] = g_lutp[i];
    if (threadIdx.x < DTOT_) s_colmap[threadIdx.x] = g_colmap[threadIdx.x];
    __syncthreads();

    const int lane = threadIdx.x & 31;
    const int warp = threadIdx.x >> 5;
    const int wpb  = blockDim.x >> 5;

    const int j0 = s_colmap[lane];
    const int j1 = s_colmap[lane + 32];
    const int jb0 = max(j0, 0);
    const int jb1 = max(j1, 0);
    const bool any0 = __any_sync(FULLM, j0 >= 0);
    const bool any1 = __any_sync(FULLM, j1 >= 0);

    const int stride = gridDim.x * wpb * 2;

    for (int row = (blockIdx.x * wpb + warp) * 2; row < N; row += stride) {
        const int  rowb  = row + 1;
        const bool haveb = rowb < N;
        const size_t ba = (size_t)row  * DTOT_;
        const size_t bb = (size_t)rowb * DTOT_;

        const float xa0 = u[ba + lane];
        const float xa1 = u[ba + lane + 32];
        const float xb0 = haveb ? u[bb + lane] : 0.0f;
        const float xb1 = haveb ? u[bb + lane + 32] : 0.0f;

        float acca = 0.0f, accb = 0.0f;
        float ya0 = xa0, ya1 = xa1, yb0 = xb0, yb1 = xb1;

        if (any0) {
            eval_one(xa0, j0, jb0, s_A, s_B2, s_lutp, ya0, acca);
            eval_one(xb0, j0, jb0, s_A, s_B2, s_lutp, yb0, accb);
        }
        if (any1) {
            eval_one(xa1, j1, jb1, s_A, s_B2, s_lutp, ya1, acca);
            eval_one(xb1, j1, jb1, s_A, s_B2, s_lutp, yb1, accb);
        }

        xout[ba + lane]      = ya0;
        xout[ba + lane + 32] = ya1;
        if (haveb) {
            xout[bb + lane]      = yb0;
            xout[bb + lane + 32] = yb1;
        }

        // Paired reduction: 5 shfls for both rows.
        // Stage 0 swaps roles: low half accumulates row a, high half row b.
        float v = (lane < 16) ? accb : acca;
        float t = __shfl_xor_sync(FULLM, v, 16);
        float r = ((lane < 16) ? acca : accb) + t;
#pragma unroll
        for (int o = 8; o; o >>= 1) r += __shfl_xor_sync(FULLM, r, o);
        if (lane == 0) logd[row] = r;
        if (lane == 16 && haveb) logd[rowb] = r;
    }
}

extern "C" void kernel_launch(void* const* d_in, const int* in_sizes, int n_in,
                              void* d_out, int out_size) {
    const float* u     = (const float*)d_in[0];
    const float* w     = (const float*)d_in[1];
    const float* h     = (const float*)d_in[2];
    const float* d     = (const float*)d_in[3];
    const int*   nodes = (const int*)  d_in[4];

    const int N = out_size - in_sizes[0];
    float* xout = (float*)d_out;
    float* logd = xout + (size_t)N * DTOT_;

    static int smem_set = 0;
    if (!smem_set) {
        cudaFuncSetAttribute(spline_kernel,
                             cudaFuncAttributeMaxDynamicSharedMemorySize, SM_TOTAL);
        smem_set = 1;
    }

    precompute_tables<<<1, 1024>>>(w, h, d, nodes);
    spline_kernel<<<592, 512, SM_TOTAL>>>(u, xout, logd, N);
}

// round 9
// speedup vs baseline: 4.2696x; 1.0214x over previous
#include <cuda_runtime.h>
#include <cstdint>

#define D_      32
#define K_      40
#define DTOT_   64
#define Bb      5.0f
#define LUTN_   128

// Transposed tables: [bin][dim] — bank depends only on dim (conflict-free gathers).
__device__ float4   g_At  [K_ * D_];     // {mcw = -cumw*ibw, ibw, ch, bh}
__device__ float2   g_B2t [K_ * D_];     // {d0, d1}
__device__ unsigned g_lutp[LUTN_ * D_];  // fp32 edge, idx in low 6 mantissa bits
__device__ int      g_colmap[DTOT_];

#define FULLM 0xffffffffu
__device__ __forceinline__ float warp_max(float v) {
#pragma unroll
    for (int o = 16; o; o >>= 1) v = fmaxf(v, __shfl_xor_sync(FULLM, v, o));
    return v;
}
__device__ __forceinline__ float warp_sum(float v) {
#pragma unroll
    for (int o = 16; o; o >>= 1) v += __shfl_xor_sync(FULLM, v, o);
    return v;
}
__device__ __forceinline__ float warp_scan(float v, int lane) {
#pragma unroll
    for (int o = 1; o < 32; o <<= 1) {
        float t = __shfl_up_sync(FULLM, v, o);
        if (lane >= o) v += t;
    }
    return v;
}

// Warp-per-dim precompute (32 warps).
__global__ void __launch_bounds__(1024)
precompute_tables(const float* __restrict__ w,
                  const float* __restrict__ h,
                  const float* __restrict__ d,
                  const int*   __restrict__ nodes) {
    __shared__ float scumw[D_][K_ + 1];
    const int tid = threadIdx.x, lane = tid & 31, j = tid >> 5;

    if (tid < DTOT_) g_colmap[tid] = -1;
    __syncthreads();
    if (tid < D_) g_colmap[nodes[tid]] = tid;

    // widths
    const float w0 = w[j * K_ + lane];
    const float w1 = (lane < 8) ? w[j * K_ + 32 + lane] : -1e30f;
    float m = warp_max(fmaxf(w0, w1));
    const float e0 = expf(w0 - m);
    const float e1 = (lane < 8) ? expf(w1 - m) : 0.0f;
    const float scl = (2.0f * Bb) / warp_sum(e0 + e1);
    const float bw0 = e0 * scl, bw1 = e1 * scl;
    float s0 = warp_scan(bw0, lane);
    const float tot0 = __shfl_sync(FULLM, s0, 31);
    float s1 = warp_scan(bw1, lane) + tot0;
    const float cw0 = -Bb + s0 - bw0, cw0n = -Bb + s0;
    const float cw1 = -Bb + s1 - bw1, cw1n = -Bb + s1;

    // heights
    const float h0 = h[j * K_ + lane];
    const float h1 = (lane < 8) ? h[j * K_ + 32 + lane] : -1e30f;
    m = warp_max(fmaxf(h0, h1));
    const float f0 = expf(h0 - m);
    const float f1 = (lane < 8) ? expf(h1 - m) : 0.0f;
    const float scl2 = (2.0f * Bb) / warp_sum(f0 + f1);
    const float bh0 = f0 * scl2, bh1 = f1 * scl2;
    float t0 = warp_scan(bh0, lane);
    const float htot0 = __shfl_sync(FULLM, t0, 31);
    float t1 = warp_scan(bh1, lane) + htot0;
    const float ch0 = -Bb + t0 - bh0;
    const float ch1 = -Bb + t1 - bh1;

    // derivatives dv(i) = (i==0||i==K)?1:softplus(d[i-1])
    const float dva0 = (lane == 0) ? 1.0f : log1pf(expf(d[j * (K_ - 1) + lane - 1]));
    const float dvb0 = log1pf(expf(d[j * (K_ - 1) + lane]));
    float dva1 = 0.f, dvb1 = 0.f;
    if (lane < 8) {
        const int i = 32 + lane;
        dva1 = log1pf(expf(d[j * (K_ - 1) + i - 1]));
        dvb1 = (i + 1 == K_) ? 1.0f : log1pf(expf(d[j * (K_ - 1) + i]));
    }

    // transposed stores: [bin][dim]; A.x = -cumw*ibw for 1-FFMA theta
    {
        const float ibw = 1.0f / bw0;
        g_At [lane * D_ + j] = make_float4(-cw0 * ibw, ibw, ch0, bh0);
        g_B2t[lane * D_ + j] = make_float2(dva0, dvb0);
        scumw[j][lane] = cw0;
    }
    if (lane < 8) {
        const int i = 32 + lane;
        const float ibw = 1.0f / bw1;
        g_At [i * D_ + j] = make_float4(-cw1 * ibw, ibw, ch1, bh1);
        g_B2t[i * D_ + j] = make_float2(dva1, dvb1);
        scumw[j][i] = cw1;
        if (i == K_ - 1) scumw[j][K_] = cw1n;
    }
    __syncwarp();

    // LUT (transposed): entry[m][j] = fp32(cumw[idx+1]) | idx (low 6 bits)
#pragma unroll
    for (int c = 0; c < 4; c++) {
        const int mm = lane * 4 + c;
        const float xm = -Bb + (2.0f * Bb) * ((float)mm / (float)LUTN_);
        int lo = 0, hi = K_;
        while (hi - lo > 1) {
            const int mid = (lo + hi) >> 1;
            if (scumw[j][mid] <= xm) lo = mid; else hi = mid;
        }
        const float edge = scumw[j][lo + 1];
        g_lutp[mm * D_ + j] = (__float_as_uint(edge) & ~63u) | (unsigned)lo;
    }
}

__device__ __forceinline__ void eval_one(
    float x, int jb,
    const float4* s_A, const float2* s_B2, const unsigned* s_lutp,
    float& y, float& acc)
{
    const float xc = fminf(fmaxf(x, -Bb), Bb);
    int m = min((int)fmaf(xc, (float)LUTN_ / (2.0f * Bb), (float)(LUTN_ / 2)),
                LUTN_ - 1);
    const unsigned e = s_lutp[m * D_ + jb];
    int idx = (int)(e & 63u);
    const float edge = __uint_as_float(e & ~63u);
    idx += (xc >= edge);
    idx = min(idx, K_ - 1);

    const float4 A  = s_A [idx * D_ + jb];
    const float2 Bv = s_B2[idx * D_ + jb];
    const float ibw = A.y, bh = A.w;
    const float dlt = bh * ibw;
    const float theta = fmaf(xc, ibw, A.x);          // (xc - cw) * ibw
    const float t2  = theta * theta;
    const float t1m = theta - t2;
    const float d0v = Bv.x, d1v = Bv.y;
    const float denom = fmaf(d0v + d1v - 2.0f * dlt, t1m, dlt);
    const float rd  = __fdividef(1.0f, denom);
    const float num = bh * fmaf(dlt, t2, d0v * t1m);
    const float ys  = fmaf(num, rd, A.z);
    const float omt = 1.0f - theta;
    const float At  = fmaf(d1v, t2, fmaf(2.0f * dlt, t1m, d0v * (omt * omt)));
    const float dr  = dlt * rd;
    const float ld  = __logf(dr * dr * At);

    const bool valid = fabsf(x) <= Bb;
    y = valid ? ys : x;
    acc += valid ? ld : 0.0f;
}

// Dynamic smem: A(20480) B2(10240) lut(16384) colmap(256)
#define SM_A_ELE  (K_ * D_)
#define SM_B_OFF  (SM_A_ELE * 16)
#define SM_L_OFF  (SM_B_OFF + SM_A_ELE * 8)
#define SM_C_OFF  (SM_L_OFF + LUTN_ * D_ * 4)
#define SM_TOTAL  (SM_C_OFF + DTOT_ * 4)

extern __shared__ unsigned char smem_raw[];

__global__ void __launch_bounds__(512)
spline_kernel(const float* __restrict__ u,
              float* __restrict__ xout,
              float* __restrict__ logd,
              int N) {
    float4*   s_A      = (float4*)smem_raw;
    float2*   s_B2     = (float2*)(smem_raw + SM_B_OFF);
    unsigned* s_lutp   = (unsigned*)(smem_raw + SM_L_OFF);
    int*      s_colmap = (int*)(smem_raw + SM_C_OFF);

    for (int i = threadIdx.x; i < SM_A_ELE; i += blockDim.x) {
        s_A[i]  = g_At[i];
        s_B2[i] = g_B2t[i];
    }
    for (int i = threadIdx.x; i < LUTN_ * D_; i += blockDim.x)
        s_lutp[i] = g_lutp[i];
    if (threadIdx.x < DTOT_) s_colmap[threadIdx.x] = g_colmap[threadIdx.x];
    __syncthreads();

    const int lane = threadIdx.x & 31;
    const int warp = threadIdx.x >> 5;
    const int wpb  = blockDim.x >> 5;

    const int j0 = s_colmap[lane];
    const int j1 = s_colmap[lane + 32];
    const int jb0 = max(j0, 0);
    const int jb1 = max(j1, 0);
    const bool do0 = __any_sync(FULLM, j0 >= 0);
    const bool do1 = __any_sync(FULLM, j1 >= 0);
    const bool v0  = (j0 >= 0);  // per-lane validity (true for all under arange nodes)
    const bool v1  = (j1 >= 0);

    const int stride  = gridDim.x * wpb * 2;               // rows per step
    const long strideF = (long)stride * DTOT_;             // floats per step

    int row = (blockIdx.x * wpb + warp) * 2;
    const float* pu = u    + (long)row * DTOT_ + lane;
    float*       px = xout + (long)row * DTOT_ + lane;
    float*       pl = logd + row;

    if (row >= N) return;

    // prologue loads
    float xa0 = pu[0], xa1 = pu[32], xb0 = pu[64], xb1 = pu[96];

    while (true) {
        const int nrow = row + stride;
        const bool more = nrow < N;
        // prefetch next pair (pointer clamped → always safe)
        const float* pun = more ? (pu + strideF) : pu;
        const float nxa0 = pun[0], nxa1 = pun[32];
        const float nxb0 = pun[64], nxb1 = pun[96];

        float acca = 0.0f, accb = 0.0f;
        float ya0 = xa0, ya1 = xa1, yb0 = xb0, yb1 = xb1;

        if (do0) {
            float t;
            eval_one(xa0, jb0, s_A, s_B2, s_lutp, t, acca); if (v0) ya0 = t;
            eval_one(xb0, jb0, s_A, s_B2, s_lutp, t, accb); if (v0) yb0 = t;
            if (!v0) { acca = 0.0f; accb = 0.0f; }
        }
        if (do1) {
            float t, a2 = 0.0f, b2 = 0.0f;
            eval_one(xa1, jb1, s_A, s_B2, s_lutp, t, a2); if (v1) { ya1 = t; acca += a2; }
            eval_one(xb1, jb1, s_A, s_B2, s_lutp, t, b2); if (v1) { yb1 = t; accb += b2; }
        }

        px[0]  = ya0;
        px[32] = ya1;
        px[64] = yb0;
        px[96] = yb1;

        // paired reduction: 5 shfls for both rows
        float v = (lane < 16) ? accb : acca;
        float tt = __shfl_xor_sync(FULLM, v, 16);
        float r = ((lane < 16) ? acca : accb) + tt;
#pragma unroll
        for (int o = 8; o; o >>= 1) r += __shfl_xor_sync(FULLM, r, o);
        if (lane == 0) pl[0] = r;
        if (lane == 16 && row + 1 < N) pl[1] = r;

        if (!more) break;
        row = nrow;
        pu  = pun;
        px += strideF;
        pl += stride;
        xa0 = nxa0; xa1 = nxa1; xb0 = nxb0; xb1 = nxb1;
    }
}

extern "C" void kernel_launch(void* const* d_in, const int* in_sizes, int n_in,
                              void* d_out, int out_size) {
    const float* u     = (const float*)d_in[0];
    const float* w     = (const float*)d_in[1];
    const float* h     = (const float*)d_in[2];
    const float* d     = (const float*)d_in[3];
    const int*   nodes = (const int*)  d_in[4];

    const int N = out_size - in_sizes[0];
    float* xout = (float*)d_out;
    float* logd = xout + (size_t)N * DTOT_;

    static int smem_set = 0;
    if (!smem_set) {
        cudaFuncSetAttribute(spline_kernel,
                             cudaFuncAttributeMaxDynamicSharedMemorySize, SM_TOTAL);
        smem_set = 1;
    }

    precompute_tables<<<1, 1024>>>(w, h, d, nodes);
    spline_kernel<<<592, 512, SM_TOTAL>>>(u, xout, logd, N);
}

// round 10
// speedup vs baseline: 5.0917x; 1.1925x over previous
#include <cuda_runtime.h>
#include <cstdint>

#define D_      32
#define K_      40
#define DTOT_   64
#define Bb      5.0f
#define LUTN_   128

// Transposed tables: [bin][dim] — bank depends only on dim (conflict-free gathers).
__device__ float4   g_At  [K_ * D_];     // {mcw = -cumw*ibw, ibw, ch, bh}
__device__ float2   g_B2t [K_ * D_];     // {d0, d1}
__device__ unsigned g_lutp[LUTN_ * D_];  // fp32 edge, idx in low 6 mantissa bits
__device__ int      g_colmap[DTOT_];

#define FULLM 0xffffffffu
__device__ __forceinline__ float warp_max(float v) {
#pragma unroll
    for (int o = 16; o; o >>= 1) v = fmaxf(v, __shfl_xor_sync(FULLM, v, o));
    return v;
}
__device__ __forceinline__ float warp_sum(float v) {
#pragma unroll
    for (int o = 16; o; o >>= 1) v += __shfl_xor_sync(FULLM, v, o);
    return v;
}
__device__ __forceinline__ float warp_scan(float v, int lane) {
#pragma unroll
    for (int o = 1; o < 32; o <<= 1) {
        float t = __shfl_up_sync(FULLM, v, o);
        if (lane >= o) v += t;
    }
    return v;
}

// Warp-per-dim precompute (32 warps).
__global__ void __launch_bounds__(1024)
precompute_tables(const float* __restrict__ w,
                  const float* __restrict__ h,
                  const float* __restrict__ d,
                  const int*   __restrict__ nodes) {
    __shared__ float scumw[D_][K_ + 1];
    const int tid = threadIdx.x, lane = tid & 31, j = tid >> 5;

    if (tid < DTOT_) g_colmap[tid] = -1;
    __syncthreads();
    if (tid < D_) g_colmap[nodes[tid]] = tid;

    // widths
    const float w0 = w[j * K_ + lane];
    const float w1 = (lane < 8) ? w[j * K_ + 32 + lane] : -1e30f;
    float m = warp_max(fmaxf(w0, w1));
    const float e0 = expf(w0 - m);
    const float e1 = (lane < 8) ? expf(w1 - m) : 0.0f;
    const float scl = (2.0f * Bb) / warp_sum(e0 + e1);
    const float bw0 = e0 * scl, bw1 = e1 * scl;
    float s0 = warp_scan(bw0, lane);
    const float tot0 = __shfl_sync(FULLM, s0, 31);
    float s1 = warp_scan(bw1, lane) + tot0;
    const float cw0 = -Bb + s0 - bw0, cw0n = -Bb + s0;
    const float cw1 = -Bb + s1 - bw1, cw1n = -Bb + s1;

    // heights
    const float h0 = h[j * K_ + lane];
    const float h1 = (lane < 8) ? h[j * K_ + 32 + lane] : -1e30f;
    m = warp_max(fmaxf(h0, h1));
    const float f0 = expf(h0 - m);
    const float f1 = (lane < 8) ? expf(h1 - m) : 0.0f;
    const float scl2 = (2.0f * Bb) / warp_sum(f0 + f1);
    const float bh0 = f0 * scl2, bh1 = f1 * scl2;
    float t0 = warp_scan(bh0, lane);
    const float htot0 = __shfl_sync(FULLM, t0, 31);
    float t1 = warp_scan(bh1, lane) + htot0;
    const float ch0 = -Bb + t0 - bh0;
    const float ch1 = -Bb + t1 - bh1;

    // derivatives dv(i) = (i==0||i==K)?1:softplus(d[i-1])
    const float dva0 = (lane == 0) ? 1.0f : log1pf(expf(d[j * (K_ - 1) + lane - 1]));
    const float dvb0 = log1pf(expf(d[j * (K_ - 1) + lane]));
    float dva1 = 0.f, dvb1 = 0.f;
    if (lane < 8) {
        const int i = 32 + lane;
        dva1 = log1pf(expf(d[j * (K_ - 1) + i - 1]));
        dvb1 = (i + 1 == K_) ? 1.0f : log1pf(expf(d[j * (K_ - 1) + i]));
    }

    // transposed stores: [bin][dim]; A.x = -cumw*ibw for 1-FFMA theta
    {
        const float ibw = 1.0f / bw0;
        g_At [lane * D_ + j] = make_float4(-cw0 * ibw, ibw, ch0, bh0);
        g_B2t[lane * D_ + j] = make_float2(dva0, dvb0);
        scumw[j][lane] = cw0;
    }
    if (lane < 8) {
        const int i = 32 + lane;
        const float ibw = 1.0f / bw1;
        g_At [i * D_ + j] = make_float4(-cw1 * ibw, ibw, ch1, bh1);
        g_B2t[i * D_ + j] = make_float2(dva1, dvb1);
        scumw[j][i] = cw1;
        if (i == K_ - 1) scumw[j][K_] = cw1n;
    }
    __syncwarp();

    // LUT (transposed): entry[m][j] = fp32(cumw[idx+1]) | idx (low 6 bits).
    // Cells already at the last bin get a NaN-pattern edge so the compare
    // (xc >= edge) is always false -> no clamp needed in the hot path.
    #pragma unroll
    for (int c = 0; c < 4; c++) {
        const int mm = lane * 4 + c;
        const float xm = -Bb + (2.0f * Bb) * ((float)mm / (float)LUTN_);
        int lo = 0, hi = K_;
        while (hi - lo > 1) {
            const int mid = (lo + hi) >> 1;
            if (scumw[j][mid] <= xm) lo = mid; else hi = mid;
        }
        unsigned bits;
        if (lo >= K_ - 1) {
            bits = (0x7fc00000u & ~63u) | (unsigned)(K_ - 1);  // NaN edge, idx=K-1
        } else {
            const float edge = scumw[j][lo + 1];
            bits = (__float_as_uint(edge) & ~63u) | (unsigned)lo;
        }
        g_lutp[mm * D_ + j] = bits;
    }
}

__device__ __forceinline__ void eval_one(
    float x, int jb, float lim,
    const float4* s_A, const float2* s_B2, const unsigned* s_lutp,
    float& y, float& acc)
{
    // clamp slightly inside B so m <= 127 with no extra min
    const float xc = fminf(fmaxf(x, -Bb), 4.9999995f);
    const int m = (int)fmaf(xc, (float)LUTN_ / (2.0f * Bb), (float)(LUTN_ / 2));
    const unsigned e = s_lutp[m * D_ + jb];
    int idx = (int)(e & 63u);
    const float edge = __uint_as_float(e & ~63u);
    idx += (xc >= edge);          // NaN edge on last bin => never increments

    const float4 A  = s_A [idx * D_ + jb];
    const float2 Bv = s_B2[idx * D_ + jb];
    const float ibw = A.y, bh = A.w;
    const float dlt = bh * ibw;
    const float theta = fmaf(xc, ibw, A.x);          // (xc - cw) * ibw
    const float t2  = theta * theta;
    const float t1m = theta - t2;
    const float d0v = Bv.x, d1v = Bv.y;
    const float denom = fmaf(d0v + d1v - 2.0f * dlt, t1m, dlt);
    const float rd  = __fdividef(1.0f, denom);
    const float num = bh * fmaf(dlt, t2, d0v * t1m);
    const float ys  = fmaf(num, rd, A.z);
    const float omt = 1.0f - theta;
    const float At  = fmaf(d1v, t2, fmaf(2.0f * dlt, t1m, d0v * (omt * omt)));
    const float dr  = dlt * rd;
    const float ld  = __logf(dr * dr * At);

    const bool valid = fabsf(x) <= lim;   // folds (j>=0) && |x|<=B
    y = valid ? ys : x;
    acc += valid ? ld : 0.0f;
}

// Dynamic smem: A(20480) B2(10240) lut(16384) colmap(256)
#define SM_A_ELE  (K_ * D_)
#define SM_B_OFF  (SM_A_ELE * 16)
#define SM_L_OFF  (SM_B_OFF + SM_A_ELE * 8)
#define SM_C_OFF  (SM_L_OFF + LUTN_ * D_ * 4)
#define SM_TOTAL  (SM_C_OFF + DTOT_ * 4)

extern __shared__ unsigned char smem_raw[];

__global__ void __launch_bounds__(512, 4)
spline_kernel(const float* __restrict__ u,
              float* __restrict__ xout,
              float* __restrict__ logd,
              int N) {
    float4*   s_A      = (float4*)smem_raw;
    float2*   s_B2     = (float2*)(smem_raw + SM_B_OFF);
    unsigned* s_lutp   = (unsigned*)(smem_raw + SM_L_OFF);
    int*      s_colmap = (int*)(smem_raw + SM_C_OFF);

    for (int i = threadIdx.x; i < SM_A_ELE; i += blockDim.x) {
        s_A[i]  = g_At[i];
        s_B2[i] = g_B2t[i];
    }
    for (int i = threadIdx.x; i < LUTN_ * D_; i += blockDim.x)
        s_lutp[i] = g_lutp[i];
    if (threadIdx.x < DTOT_) s_colmap[threadIdx.x] = g_colmap[threadIdx.x];
    __syncthreads();

    const int lane = threadIdx.x & 31;
    const int warp = threadIdx.x >> 5;
    const int wpb  = blockDim.x >> 5;

    const int j0 = s_colmap[lane];
    const int j1 = s_colmap[lane + 32];
    const int jb0 = max(j0, 0);
    const int jb1 = max(j1, 0);
    const float lim0 = (j0 >= 0) ? Bb : -1.0f;
    const float lim1 = (j1 >= 0) ? Bb : -1.0f;
    const bool do0 = __any_sync(FULLM, j0 >= 0);
    const bool do1 = __any_sync(FULLM, j1 >= 0);

    const int  stride  = gridDim.x * wpb * 2;     // rows per step
    const long strideF = (long)stride * DTOT_;

    int row = (blockIdx.x * wpb + warp) * 2;
    const float* pu = u    + (long)row * DTOT_ + lane;
    float*       px = xout + (long)row * DTOT_ + lane;
    float*       pl = logd + row;

    for (; row < N; row += stride, pu += strideF, px += strideF, pl += stride) {
        const float xa0 = pu[0], xa1 = pu[32], xb0 = pu[64], xb1 = pu[96];

        float acca = 0.0f, accb = 0.0f;
        float ya0 = xa0, ya1 = xa1, yb0 = xb0, yb1 = xb1;

        if (do0) {
            eval_one(xa0, jb0, lim0, s_A, s_B2, s_lutp, ya0, acca);
            eval_one(xb0, jb0, lim0, s_A, s_B2, s_lutp, yb0, accb);
        }
        if (do1) {
            eval_one(xa1, jb1, lim1, s_A, s_B2, s_lutp, ya1, acca);
            eval_one(xb1, jb1, lim1, s_A, s_B2, s_lutp, yb1, accb);
        }

        px[0]  = ya0;
        px[32] = ya1;
        px[64] = yb0;
        px[96] = yb1;

        // paired reduction: 5 shfls for both rows
        float v = (lane < 16) ? accb : acca;
        float tt = __shfl_xor_sync(FULLM, v, 16);
        float r = ((lane < 16) ? acca : accb) + tt;
#pragma unroll
        for (int o = 8; o; o >>= 1) r += __shfl_xor_sync(FULLM, r, o);
        if (lane == 0) pl[0] = r;
        if (lane == 16 && row + 1 < N) pl[1] = r;
    }
}

extern "C" void kernel_launch(void* const* d_in, const int* in_sizes, int n_in,
                              void* d_out, int out_size) {
    const float* u     = (const float*)d_in[0];
    const float* w     = (const float*)d_in[1];
    const float* h     = (const float*)d_in[2];
    const float* d     = (const float*)d_in[3];
    const int*   nodes = (const int*)  d_in[4];

    const int N = out_size - in_sizes[0];
    float* xout = (float*)d_out;
    float* logd = xout + (size_t)N * DTOT_;

    static int smem_set = 0;
    if (!smem_set) {
        cudaFuncSetAttribute(spline_kernel,
                             cudaFuncAttributeMaxDynamicSharedMemorySize, SM_TOTAL);
        smem_set = 1;
    }

    precompute_tables<<<1, 1024>>>(w, h, d, nodes);
    spline_kernel<<<592, 512, SM_TOTAL>>>(u, xout, logd, N);
}

// round 11
// speedup vs baseline: 5.3051x; 1.0419x over previous
#include <cuda_runtime.h>
#include <cstdint>

#define D_      32
#define K_      40
#define DTOT_   64
#define Bb      5.0f
#define LUTN_   128

// Transposed tables: [bin][dim] — bank depends only on dim (conflict-free gathers).
__device__ float4   g_At  [K_ * D_];     // {mcw = -cumw*ibw, ibw, ch, bh}
__device__ float2   g_B2t [K_ * D_];     // {d0, d1}
__device__ unsigned g_lutp[LUTN_ * D_];  // fp32 edge, idx in low 6 mantissa bits
__device__ int      g_colmap[DTOT_];

#define FULLM 0xffffffffu
__device__ __forceinline__ float warp_max(float v) {
#pragma unroll
    for (int o = 16; o; o >>= 1) v = fmaxf(v, __shfl_xor_sync(FULLM, v, o));
    return v;
}
__device__ __forceinline__ float warp_sum(float v) {
#pragma unroll
    for (int o = 16; o; o >>= 1) v += __shfl_xor_sync(FULLM, v, o);
    return v;
}
__device__ __forceinline__ float warp_scan(float v, int lane) {
#pragma unroll
    for (int o = 1; o < 32; o <<= 1) {
        float t = __shfl_up_sync(FULLM, v, o);
        if (lane >= o) v += t;
    }
    return v;
}

// Warp-per-dim precompute (32 warps).
__global__ void __launch_bounds__(1024)
precompute_tables(const float* __restrict__ w,
                  const float* __restrict__ h,
                  const float* __restrict__ d,
                  const int*   __restrict__ nodes) {
    __shared__ float scumw[D_][K_ + 1];
    const int tid = threadIdx.x, lane = tid & 31, j = tid >> 5;

    if (tid < DTOT_) g_colmap[tid] = -1;
    __syncthreads();
    if (tid < D_) g_colmap[nodes[tid]] = tid;

    // widths
    const float w0 = w[j * K_ + lane];
    const float w1 = (lane < 8) ? w[j * K_ + 32 + lane] : -1e30f;
    float m = warp_max(fmaxf(w0, w1));
    const float e0 = expf(w0 - m);
    const float e1 = (lane < 8) ? expf(w1 - m) : 0.0f;
    const float scl = (2.0f * Bb) / warp_sum(e0 + e1);
    const float bw0 = e0 * scl, bw1 = e1 * scl;
    float s0 = warp_scan(bw0, lane);
    const float tot0 = __shfl_sync(FULLM, s0, 31);
    float s1 = warp_scan(bw1, lane) + tot0;
    const float cw0 = -Bb + s0 - bw0, cw0n = -Bb + s0;
    const float cw1 = -Bb + s1 - bw1, cw1n = -Bb + s1;

    // heights
    const float h0 = h[j * K_ + lane];
    const float h1 = (lane < 8) ? h[j * K_ + 32 + lane] : -1e30f;
    m = warp_max(fmaxf(h0, h1));
    const float f0 = expf(h0 - m);
    const float f1 = (lane < 8) ? expf(h1 - m) : 0.0f;
    const float scl2 = (2.0f * Bb) / warp_sum(f0 + f1);
    const float bh0 = f0 * scl2, bh1 = f1 * scl2;
    float t0 = warp_scan(bh0, lane);
    const float htot0 = __shfl_sync(FULLM, t0, 31);
    float t1 = warp_scan(bh1, lane) + htot0;
    const float ch0 = -Bb + t0 - bh0;
    const float ch1 = -Bb + t1 - bh1;

    // derivatives dv(i) = (i==0||i==K)?1:softplus(d[i-1])
    const float dva0 = (lane == 0) ? 1.0f : log1pf(expf(d[j * (K_ - 1) + lane - 1]));
    const float dvb0 = log1pf(expf(d[j * (K_ - 1) + lane]));
    float dva1 = 0.f, dvb1 = 0.f;
    if (lane < 8) {
        const int i = 32 + lane;
        dva1 = log1pf(expf(d[j * (K_ - 1) + i - 1]));
        dvb1 = (i + 1 == K_) ? 1.0f : log1pf(expf(d[j * (K_ - 1) + i]));
    }

    // transposed stores: [bin][dim]; A.x = -cumw*ibw for 1-FFMA theta
    {
        const float ibw = 1.0f / bw0;
        g_At [lane * D_ + j] = make_float4(-cw0 * ibw, ibw, ch0, bh0);
        g_B2t[lane * D_ + j] = make_float2(dva0, dvb0);
        scumw[j][lane] = cw0;
    }
    if (lane < 8) {
        const int i = 32 + lane;
        const float ibw = 1.0f / bw1;
        g_At [i * D_ + j] = make_float4(-cw1 * ibw, ibw, ch1, bh1);
        g_B2t[i * D_ + j] = make_float2(dva1, dvb1);
        scumw[j][i] = cw1;
        if (i == K_ - 1) scumw[j][K_] = cw1n;
    }
    __syncwarp();

    // LUT: entry[m][j] = fp32(cumw[idx+1]) | idx (low 6 bits); NaN edge on last bin.
    #pragma unroll
    for (int c = 0; c < 4; c++) {
        const int mm = lane * 4 + c;
        const float xm = -Bb + (2.0f * Bb) * ((float)mm / (float)LUTN_);
        int lo = 0, hi = K_;
        while (hi - lo > 1) {
            const int mid = (lo + hi) >> 1;
            if (scumw[j][mid] <= xm) lo = mid; else hi = mid;
        }
        unsigned bits;
        if (lo >= K_ - 1) {
            bits = (0x7fc00000u & ~63u) | (unsigned)(K_ - 1);
        } else {
            const float edge = scumw[j][lo + 1];
            bits = (__float_as_uint(edge) & ~63u) | (unsigned)lo;
        }
        g_lutp[mm * D_ + j] = bits;
    }
}

__device__ __forceinline__ void eval_one(
    float x, int jb, float lim,
    const float4* s_A, const float2* s_B2, const unsigned* s_lutp,
    float& y, float& acc)
{
    const float xc = fminf(fmaxf(x, -Bb), 4.9999995f);
    const int m = (int)fmaf(xc, (float)LUTN_ / (2.0f * Bb), (float)(LUTN_ / 2));
    const unsigned e = s_lutp[m * D_ + jb];
    int idx = (int)(e & 63u);
    const float edge = __uint_as_float(e & ~63u);
    idx += (xc >= edge);          // NaN edge on last bin => never increments

    const float4 A  = s_A [idx * D_ + jb];
    const float2 Bv = s_B2[idx * D_ + jb];
    const float ibw = A.y, bh = A.w;
    const float dlt = bh * ibw;
    const float theta = fmaf(xc, ibw, A.x);
    const float t2  = theta * theta;
    const float t1m = theta - t2;
    const float d0v = Bv.x, d1v = Bv.y;
    const float denom = fmaf(d0v + d1v - 2.0f * dlt, t1m, dlt);
    const float rd  = __fdividef(1.0f, denom);
    const float num = bh * fmaf(dlt, t2, d0v * t1m);
    const float ys  = fmaf(num, rd, A.z);
    const float omt = 1.0f - theta;
    const float At  = fmaf(d1v, t2, fmaf(2.0f * dlt, t1m, d0v * (omt * omt)));
    const float dr  = dlt * rd;
    const float ld  = __logf(dr * dr * At);

    const bool valid = fabsf(x) <= lim;
    y = valid ? ys : x;
    acc += valid ? ld : 0.0f;
}

// Dynamic smem: A(20480) B2(10240) lut(16384) colmap(256)
#define SM_A_ELE  (K_ * D_)
#define SM_B_OFF  (SM_A_ELE * 16)
#define SM_L_OFF  (SM_B_OFF + SM_A_ELE * 8)
#define SM_C_OFF  (SM_L_OFF + LUTN_ * D_ * 4)
#define SM_TOTAL  (SM_C_OFF + DTOT_ * 4)

extern __shared__ unsigned char smem_raw[];

__global__ void __launch_bounds__(512, 3)
spline_kernel(const float* __restrict__ u,
              float* __restrict__ xout,
              float* __restrict__ logd,
              int N) {
    float4*   s_A      = (float4*)smem_raw;
    float2*   s_B2     = (float2*)(smem_raw + SM_B_OFF);
    unsigned* s_lutp   = (unsigned*)(smem_raw + SM_L_OFF);
    int*      s_colmap = (int*)(smem_raw + SM_C_OFF);

    for (int i = threadIdx.x; i < SM_A_ELE; i += blockDim.x) {
        s_A[i]  = g_At[i];
        s_B2[i] = g_B2t[i];
    }
    for (int i = threadIdx.x; i < LUTN_ * D_; i += blockDim.x)
        s_lutp[i] = g_lutp[i];
    if (threadIdx.x < DTOT_) s_colmap[threadIdx.x] = g_colmap[threadIdx.x];
    __syncthreads();

    const int lane = threadIdx.x & 31;
    const int warp = threadIdx.x >> 5;
    const int wpb  = blockDim.x >> 5;

    const int j0 = s_colmap[lane];
    const int j1 = s_colmap[lane + 32];
    const int jb0 = max(j0, 0);
    const int jb1 = max(j1, 0);
    const float lim0 = (j0 >= 0) ? Bb : -1.0f;
    const float lim1 = (j1 >= 0) ? Bb : -1.0f;
    const bool do0 = __any_sync(FULLM, j0 >= 0);
    const bool do1 = __any_sync(FULLM, j1 >= 0);

    const int  stride  = gridDim.x * wpb * 4;     // rows per step (quads)
    const long strideF = (long)stride * DTOT_;

    int row = (blockIdx.x * wpb + warp) * 4;
    const float* pu = u    + (long)row * DTOT_ + lane;
    float*       px = xout + (long)row * DTOT_ + lane;
    float*       pl = logd + row;

    for (; row < N; row += stride, pu += strideF, px += strideF, pl += stride) {
        if (row + 3 < N) {
            // ---- fast path: 8 independent loads up front (MLP=8) ----
            const float a0 = pu[0],   a1 = pu[32];
            const float b0 = pu[64],  b1 = pu[96];
            const float c0 = pu[128], c1 = pu[160];
            const float d0 = pu[192], d1 = pu[224];

            float aa = 0.f, ab = 0.f, ac = 0.f, ad = 0.f;
            float ya0 = a0, ya1 = a1, yb0 = b0, yb1 = b1;
            float yc0 = c0, yc1 = c1, yd0 = d0, yd1 = d1;

            if (do0) {
                eval_one(a0, jb0, lim0, s_A, s_B2, s_lutp, ya0, aa);
                eval_one(b0, jb0, lim0, s_A, s_B2, s_lutp, yb0, ab);
                eval_one(c0, jb0, lim0, s_A, s_B2, s_lutp, yc0, ac);
                eval_one(d0, jb0, lim0, s_A, s_B2, s_lutp, yd0, ad);
            }
            if (do1) {
                eval_one(a1, jb1, lim1, s_A, s_B2, s_lutp, ya1, aa);
                eval_one(b1, jb1, lim1, s_A, s_B2, s_lutp, yb1, ab);
                eval_one(c1, jb1, lim1, s_A, s_B2, s_lutp, yc1, ac);
                eval_one(d1, jb1, lim1, s_A, s_B2, s_lutp, yd1, ad);
            }

            px[0]   = ya0;  px[32]  = ya1;
            px[64]  = yb0;  px[96]  = yb1;
            px[128] = yc0;  px[160] = yc1;
            px[192] = yd0;  px[224] = yd1;

            // paired reductions (5 shfls per pair)
            {
                float v = (lane < 16) ? ab : aa;
                float t = __shfl_xor_sync(FULLM, v, 16);
                float r = ((lane < 16) ? aa : ab) + t;
#pragma unroll
                for (int o = 8; o; o >>= 1) r += __shfl_xor_sync(FULLM, r, o);
                if (lane == 0)  pl[0] = r;
                if (lane == 16) pl[1] = r;
            }
            {
                float v = (lane < 16) ? ad : ac;
                float t = __shfl_xor_sync(FULLM, v, 16);
                float r = ((lane < 16) ? ac : ad) + t;
#pragma unroll
                for (int o = 8; o; o >>= 1) r += __shfl_xor_sync(FULLM, r, o);
                if (lane == 0)  pl[2] = r;
                if (lane == 16) pl[3] = r;
            }
        } else {
            // ---- tail: per-row guarded ----
            for (int r = 0; r < 4 && row + r < N; r++) {
                const float x0 = pu[r * 64];
                const float x1 = pu[r * 64 + 32];
                float acc = 0.f, y0 = x0, y1 = x1;
                if (do0) eval_one(x0, jb0, lim0, s_A, s_B2, s_lutp, y0, acc);
                if (do1) eval_one(x1, jb1, lim1, s_A, s_B2, s_lutp, y1, acc);
                px[r * 64]      = y0;
                px[r * 64 + 32] = y1;
#pragma unroll
                for (int o = 16; o; o >>= 1) acc += __shfl_xor_sync(FULLM, acc, o);
                if (lane == 0) pl[r] = acc;
            }
        }
    }
}

extern "C" void kernel_launch(void* const* d_in, const int* in_sizes, int n_in,
                              void* d_out, int out_size) {
    const float* u     = (const float*)d_in[0];
    const float* w     = (const float*)d_in[1];
    const float* h     = (const float*)d_in[2];
    const float* d     = (const float*)d_in[3];
    const int*   nodes = (const int*)  d_in[4];

    const int N = out_size - in_sizes[0];
    float* xout = (float*)d_out;
    float* logd = xout + (size_t)N * DTOT_;

    static int smem_set = 0;
    if (!smem_set) {
        cudaFuncSetAttribute(spline_kernel,
                             cudaFuncAttributeMaxDynamicSharedMemorySize, SM_TOTAL);
        smem_set = 1;
    }

    precompute_tables<<<1, 1024>>>(w, h, d, nodes);
    spline_kernel<<<444, 512, SM_TOTAL>>>(u, xout, logd, N);
}